// round 1
// baseline (speedup 1.0000x reference)
#include <cuda_runtime.h>
#include <cuda_bf16.h>

// Conv2d 3x3 s1 p1: N=32, Cin=128, Cout=256, H=W=56, fp32.
// Implicit GEMM: A = weight [256,1152] (row-major as given),
//                B = im2col(x) [1152, 100352], C = out [256, 100352]
// Block tile 128x128, BK=16, 256 threads, 8x8 per-thread microtile.

#define IN_C   128
#define OUT_C  256
#define HW     56
#define SP     3136      // 56*56
#define NKDIM  1152      // 128*9
#define NSPAT  100352    // 32*3136

#define BM 128
#define BN 128
#define BK 16
#define TM 8
#define TN 8

__global__ __launch_bounds__(256, 2)
void conv_igemm_kernel(const float* __restrict__ x,
                       const float* __restrict__ w,
                       const float* __restrict__ bias,
                       float* __restrict__ out)
{
    __shared__ float As[BK][BM];   // A staged transposed: As[k][m]
    __shared__ float Bs[BK][BN];

    const int tid = threadIdx.x;
    const int bn0 = blockIdx.x * BN;   // spatial (gemm N)
    const int bm0 = blockIdx.y * BM;   // out-channel (gemm M)

    const int tm = (tid >> 4) * TM;    // 0..120
    const int tn = (tid & 15) * TN;    // 0..120

    float acc[TM][TN];
    #pragma unroll
    for (int i = 0; i < TM; i++)
        #pragma unroll
        for (int j = 0; j < TN; j++)
            acc[i][j] = 0.0f;

    for (int k0 = 0; k0 < NKDIM; k0 += BK) {
        // --- stage A: 128x16 floats = 512 float4, 2 per thread ---
        #pragma unroll
        for (int j = 0; j < 2; j++) {
            int idx = tid + j * 256;          // 0..511
            int m   = idx >> 2;               // 0..127
            int kq  = (idx & 3) << 2;         // 0,4,8,12
            float4 v = *reinterpret_cast<const float4*>(
                &w[(bm0 + m) * NKDIM + k0 + kq]);
            As[kq + 0][m] = v.x;
            As[kq + 1][m] = v.y;
            As[kq + 2][m] = v.z;
            As[kq + 3][m] = v.w;
        }
        // --- stage B: 16x128 floats, 8 scalars per thread (im2col gather) ---
        #pragma unroll
        for (int j = 0; j < 8; j++) {
            int idx = tid + j * 256;          // 0..2047
            int kk  = idx >> 7;               // 0..15
            int nn  = idx & 127;
            int k   = k0 + kk;
            int ic  = k / 9;
            int r   = k - ic * 9;
            int kh  = r / 3;
            int kw  = r - kh * 3;
            int n   = bn0 + nn;
            int b   = n / SP;
            int s   = n - b * SP;
            int oh  = s / HW;
            int ow  = s - oh * HW;
            int ih  = oh + kh - 1;
            int iw  = ow + kw - 1;
            float v = 0.0f;
            if ((unsigned)ih < (unsigned)HW && (unsigned)iw < (unsigned)HW)
                v = x[((b * IN_C + ic) * HW + ih) * HW + iw];
            Bs[kk][nn] = v;
        }
        __syncthreads();

        // --- compute: 16 k-steps, 8x8 FFMA each ---
        #pragma unroll
        for (int kk = 0; kk < BK; kk++) {
            float a[TM], bb[TN];
            #pragma unroll
            for (int i = 0; i < TM; i++) a[i]  = As[kk][tm + i];
            #pragma unroll
            for (int j = 0; j < TN; j++) bb[j] = Bs[kk][tn + j];
            #pragma unroll
            for (int i = 0; i < TM; i++)
                #pragma unroll
                for (int j = 0; j < TN; j++)
                    acc[i][j] = fmaf(a[i], bb[j], acc[i][j]);
        }
        __syncthreads();
    }

    // --- epilogue: out layout [b, oc, oh, ow] = [(b*256+oc)*3136 + s] ---
    #pragma unroll
    for (int j = 0; j < TN; j++) {
        int n = bn0 + tn + j;
        int b = n / SP;
        int s = n - b * SP;
        #pragma unroll
        for (int i = 0; i < TM; i++) {
            int oc = bm0 + tm + i;
            out[(b * OUT_C + oc) * SP + s] = acc[i][j] + bias[oc];
        }
    }
}

extern "C" void kernel_launch(void* const* d_in, const int* in_sizes, int n_in,
                              void* d_out, int out_size)
{
    const float* x    = (const float*)d_in[0];   // 32*128*56*56
    const float* w    = (const float*)d_in[1];   // 256*128*3*3
    const float* bias = (const float*)d_in[2];   // 256
    float* out        = (float*)d_out;           // 32*256*56*56

    dim3 grid(NSPAT / BN, OUT_C / BM);           // 784 x 2
    dim3 block(256);
    conv_igemm_kernel<<<grid, block>>>(x, w, bias, out);
}

// round 3
// speedup vs baseline: 2.7678x; 2.7678x over previous
#include <cuda_runtime.h>
#include <cuda_bf16.h>
#include <cstdint>

// Conv2d 3x3 s1 p1 (N=32, Cin=128, Cout=256, 56x56, fp32) via implicit GEMM on
// warp-level mma.sync bf16 tensor cores (base sm_103 PTX — tcgen05 unavailable
// in this harness toolchain). fp32 emulated with hi/lo bf16 split (3 MMA terms).
// Prepass kernels split w and zero-padded x into __device__ bf16 scratch once.

#define IN_C   128
#define OUT_C  256
#define HW     56
#define SP     3136
#define NKDIM  1152
#define NSPAT  100352
#define XPH    58
#define XPW    58
#define XPC    (XPH * XPW)       // 3364

#define BM 128
#define BN 128
#define BK 32
#define NCH (NKDIM / BK)         // 36
#define THREADS 256

// smem layout (bytes), per buffer: Ahi | Alo | Bhi | Blo
#define A_STRIDE 80              // 32 bf16 = 64B + 16B pad
#define B_STRIDE 272             // 128 bf16 = 256B + 16B pad
#define A_BYTES  (128 * A_STRIDE)                 // 10240
#define B_BYTES  (32 * B_STRIDE)                  // 8704
#define BUF_BYTES (2 * A_BYTES + 2 * B_BYTES)     // 37888
#define SMEM_TOTAL (2 * BUF_BYTES)                // 75776

__device__ __align__(16) __nv_bfloat16 g_whi[OUT_C * NKDIM];
__device__ __align__(16) __nv_bfloat16 g_wlo[OUT_C * NKDIM];
__device__ __align__(16) __nv_bfloat16 g_xhi[32 * IN_C * XPC];
__device__ __align__(16) __nv_bfloat16 g_xlo[32 * IN_C * XPC];

#define LDSM4(r, addr) \
    asm volatile("ldmatrix.sync.aligned.m8n8.x4.shared.b16 {%0,%1,%2,%3}, [%4];" \
        : "=r"((r)[0]), "=r"((r)[1]), "=r"((r)[2]), "=r"((r)[3]) : "r"(addr))

#define LDSM4T(r0, r1, r2, r3, addr) \
    asm volatile("ldmatrix.sync.aligned.m8n8.x4.trans.shared.b16 {%0,%1,%2,%3}, [%4];" \
        : "=r"(r0), "=r"(r1), "=r"(r2), "=r"(r3) : "r"(addr))

#define MMA(d, a, b) \
    asm volatile("mma.sync.aligned.m16n8k16.row.col.f32.bf16.bf16.f32 " \
        "{%0,%1,%2,%3}, {%4,%5,%6,%7}, {%8,%9}, {%0,%1,%2,%3};" \
        : "+f"((d)[0]), "+f"((d)[1]), "+f"((d)[2]), "+f"((d)[3]) \
        : "r"((a)[0]), "r"((a)[1]), "r"((a)[2]), "r"((a)[3]), \
          "r"((b)[0]), "r"((b)[1]))

// ---------------- prepass: split into bf16 hi/lo ----------------

__global__ void split_w_kernel(const float* __restrict__ w) {
    int i = blockIdx.x * blockDim.x + threadIdx.x;
    if (i >= OUT_C * NKDIM) return;
    float v = w[i];
    __nv_bfloat16 h = __float2bfloat16(v);
    g_whi[i] = h;
    g_wlo[i] = __float2bfloat16(v - __bfloat162float(h));
}

__global__ void split_x_kernel(const float* __restrict__ x) {
    int i = blockIdx.x * blockDim.x + threadIdx.x;
    if (i >= 32 * IN_C * XPC) return;
    int iw = i % XPW;
    int t  = i / XPW;
    int ih = t % XPH;
    int c  = t / XPH;                 // b*128 + ic
    float v = 0.0f;
    if (ih >= 1 && ih <= HW && iw >= 1 && iw <= HW)
        v = x[c * SP + (ih - 1) * HW + (iw - 1)];
    __nv_bfloat16 h = __float2bfloat16(v);
    g_xhi[i] = h;
    g_xlo[i] = __float2bfloat16(v - __bfloat162float(h));
}

// ---------------- staging ----------------

__device__ __forceinline__ void stage_chunk(
    char* smc, int bufb, int ch, int tid, int bm0,
    int cbase, int ngrp, int krow0)
{
    const int k0 = ch * BK;
    // A: weights hi/lo, 128m x 32k each, 16B vector copies
    #pragma unroll
    for (int g = 0; g < 2; g++) {
        int idx = tid + 256 * g;            // 0..511
        int m   = idx >> 2;                 // 0..127
        int c4  = idx & 3;                  // 16B chunk within 64B row
        const char* sh = (const char*)(g_whi + (bm0 + m) * NKDIM + k0) + c4 * 16;
        const char* sl = (const char*)(g_wlo + (bm0 + m) * NKDIM + k0) + c4 * 16;
        uint4 vh = *(const uint4*)sh;
        uint4 vl = *(const uint4*)sl;
        *(uint4*)(smc + bufb + m * A_STRIDE + c4 * 16) = vh;
        *(uint4*)(smc + bufb + A_BYTES + m * A_STRIDE + c4 * 16) = vl;
    }
    // B: im2col gather from padded bf16 images; smem [k][n]
    const unsigned short* xhi = (const unsigned short*)g_xhi;
    const unsigned short* xlo = (const unsigned short*)g_xlo;
    #pragma unroll
    for (int kk = 0; kk < 2; kk++) {
        int krow = krow0 + kk * 16;         // 0..31
        int kg = k0 + krow;
        int ic = kg / 9;
        int r  = kg - ic * 9;
        int kh = r / 3;
        int kw = r - kh * 3;
        int base = cbase + ic * XPC + kh * XPW + kw;
        unsigned short* dh = (unsigned short*)(smc + bufb + 2 * A_BYTES
                                               + krow * B_STRIDE + ngrp * 16);
        unsigned short* dl = (unsigned short*)((char*)dh + B_BYTES);
        #pragma unroll
        for (int j = 0; j < 8; j++) {
            dh[j] = xhi[base + j];
            dl[j] = xlo[base + j];
        }
    }
}

// ---------------- main GEMM kernel ----------------

__global__ __launch_bounds__(THREADS, 2)
void conv_mma_kernel(const float* __restrict__ bias, float* __restrict__ out)
{
    extern __shared__ char smc[];
    const int tid = threadIdx.x;
    const int lid = tid & 31;
    const int wid = tid >> 5;
    const int bn0 = blockIdx.x * BN;
    const int bm0 = blockIdx.y * BM;
    const int wm0 = (wid >> 2) * 64;        // warp m offset (2 rows of warps)
    const int wn0 = (wid & 3) * 32;         // warp n offset (4 cols of warps)

    // B staging address precompute: this thread's n-group of 8 pixels
    const int ngrp = tid & 15;
    const int krow0 = tid >> 4;             // 0..15
    int cbase;
    {
        int n0 = bn0 + ngrp * 8;
        int b  = n0 / SP;
        int s  = n0 - b * SP;
        int oh = s / HW;
        int ow0 = s - oh * HW;               // multiple of 8 (56 % 8 == 0)
        cbase = (b * IN_C) * XPC + oh * XPW + ow0;
    }

    const uint32_t sb = (uint32_t)__cvta_generic_to_shared(smc);

    float acc[4][4][4];
    #pragma unroll
    for (int mt = 0; mt < 4; mt++)
        #pragma unroll
        for (int nt = 0; nt < 4; nt++)
            #pragma unroll
            for (int q = 0; q < 4; q++)
                acc[mt][nt][q] = 0.0f;

    stage_chunk(smc, 0, 0, tid, bm0, cbase, ngrp, krow0);
    __syncthreads();

    int buf = 0;
    #pragma unroll 1
    for (int ch = 0; ch < NCH; ch++) {
        const int cur = buf * BUF_BYTES;
        if (ch + 1 < NCH)
            stage_chunk(smc, (buf ^ 1) * BUF_BYTES, ch + 1, tid, bm0,
                        cbase, ngrp, krow0);

        const uint32_t ah = sb + cur;
        const uint32_t al = ah + A_BYTES;
        const uint32_t bh = al + A_BYTES;
        const uint32_t bl = bh + B_BYTES;

        #pragma unroll
        for (int ks = 0; ks < 2; ks++) {
            uint32_t a_hi[4][4], a_lo[4][4], bfr[4][2];
            const uint32_t aoff = (uint32_t)((wm0 + (lid & 15)) * A_STRIDE
                                             + ks * 32 + (lid >> 4) * 16);
            #pragma unroll
            for (int mt = 0; mt < 4; mt++) {
                LDSM4(a_hi[mt], ah + aoff + mt * 16 * A_STRIDE);
                LDSM4(a_lo[mt], al + aoff + mt * 16 * A_STRIDE);
            }
            const uint32_t boff = (uint32_t)(
                (ks * 16 + (lid & 7) + ((lid >> 3) & 1) * 8) * B_STRIDE
                + (wn0 + (lid >> 4) * 8) * 2);

            LDSM4T(bfr[0][0], bfr[0][1], bfr[1][0], bfr[1][1], bh + boff);
            LDSM4T(bfr[2][0], bfr[2][1], bfr[3][0], bfr[3][1], bh + boff + 32);
            #pragma unroll
            for (int mt = 0; mt < 4; mt++)
                #pragma unroll
                for (int nt = 0; nt < 4; nt++) {
                    MMA(acc[mt][nt], a_hi[mt], bfr[nt]);   // hi*hi
                    MMA(acc[mt][nt], a_lo[mt], bfr[nt]);   // lo*hi
                }

            LDSM4T(bfr[0][0], bfr[0][1], bfr[1][0], bfr[1][1], bl + boff);
            LDSM4T(bfr[2][0], bfr[2][1], bfr[3][0], bfr[3][1], bl + boff + 32);
            #pragma unroll
            for (int mt = 0; mt < 4; mt++)
                #pragma unroll
                for (int nt = 0; nt < 4; nt++)
                    MMA(acc[mt][nt], a_hi[mt], bfr[nt]);   // hi*lo
        }
        __syncthreads();
        buf ^= 1;
    }

    // epilogue: c-fragment direct stores (8B, sector-aligned pairs)
    #pragma unroll
    for (int nt = 0; nt < 4; nt++) {
        int n = bn0 + wn0 + nt * 8 + 2 * (lid & 3);
        int b = n / SP;
        int s = n - b * SP;
        #pragma unroll
        for (int mt = 0; mt < 4; mt++) {
            int oc0 = bm0 + wm0 + mt * 16 + (lid >> 2);
            float bv0 = __ldg(&bias[oc0]);
            float bv1 = __ldg(&bias[oc0 + 8]);
            float2 v0 = make_float2(acc[mt][nt][0] + bv0, acc[mt][nt][1] + bv0);
            float2 v1 = make_float2(acc[mt][nt][2] + bv1, acc[mt][nt][3] + bv1);
            *(float2*)&out[(b * OUT_C + oc0) * SP + s] = v0;
            *(float2*)&out[(b * OUT_C + oc0 + 8) * SP + s] = v1;
        }
    }
}

extern "C" void kernel_launch(void* const* d_in, const int* in_sizes, int n_in,
                              void* d_out, int out_size)
{
    const float* x    = (const float*)d_in[0];
    const float* w    = (const float*)d_in[1];
    const float* bias = (const float*)d_in[2];
    float* out        = (float*)d_out;

    int wtot = OUT_C * NKDIM;
    split_w_kernel<<<(wtot + 255) / 256, 256>>>(w);
    int xtot = 32 * IN_C * XPC;
    split_x_kernel<<<(xtot + 255) / 256, 256>>>(x);

    cudaFuncSetAttribute(conv_mma_kernel,
                         cudaFuncAttributeMaxDynamicSharedMemorySize, SMEM_TOTAL);
    dim3 grid(NSPAT / BN, OUT_C / BM);      // 784 x 2
    conv_mma_kernel<<<grid, THREADS, SMEM_TOTAL>>>(bias, out);
}

// round 4
// speedup vs baseline: 5.2911x; 1.9117x over previous
#include <cuda_runtime.h>
#include <cuda_fp16.h>
#include <cstdint>

// Conv2d 3x3 s1 p1 (N=32, Cin=128, Cout=256, 56x56, fp32) via implicit GEMM on
// warp-level mma.sync fp16 tensor cores, single pass (error budget: fp16 input
// rounding gives ~4e-4 global rel err vs 1e-3 gate). Prepass converts w and
// zero-padded x to fp16 in __device__ scratch.

#define IN_C   128
#define OUT_C  256
#define HW     56
#define SP     3136
#define NKDIM  1152
#define NSPAT  100352
#define XPH    58
#define XPW    58
#define XPC    (XPH * XPW)       // 3364

#define BM 128
#define BN 128
#define BK 32
#define NCH (NKDIM / BK)         // 36
#define THREADS 256

// smem layout (bytes), per buffer: A | B
#define A_STRIDE 80              // 32 fp16 = 64B + 16B pad
#define B_STRIDE 272             // 128 fp16 = 256B + 16B pad
#define A_BYTES  (128 * A_STRIDE)            // 10240
#define B_BYTES  (32 * B_STRIDE)             // 8704
#define BUF_BYTES (A_BYTES + B_BYTES)        // 18944
#define SMEM_TOTAL (2 * BUF_BYTES)           // 37888

__device__ __align__(16) __half g_wh[OUT_C * NKDIM];
__device__ __align__(16) __half g_xh[32 * IN_C * XPC];

#define LDSM4(r, addr) \
    asm volatile("ldmatrix.sync.aligned.m8n8.x4.shared.b16 {%0,%1,%2,%3}, [%4];" \
        : "=r"((r)[0]), "=r"((r)[1]), "=r"((r)[2]), "=r"((r)[3]) : "r"(addr))

#define LDSM4T(r0, r1, r2, r3, addr) \
    asm volatile("ldmatrix.sync.aligned.m8n8.x4.trans.shared.b16 {%0,%1,%2,%3}, [%4];" \
        : "=r"(r0), "=r"(r1), "=r"(r2), "=r"(r3) : "r"(addr))

#define MMA(d, a, b) \
    asm volatile("mma.sync.aligned.m16n8k16.row.col.f32.f16.f16.f32 " \
        "{%0,%1,%2,%3}, {%4,%5,%6,%7}, {%8,%9}, {%0,%1,%2,%3};" \
        : "+f"((d)[0]), "+f"((d)[1]), "+f"((d)[2]), "+f"((d)[3]) \
        : "r"((a)[0]), "r"((a)[1]), "r"((a)[2]), "r"((a)[3]), \
          "r"((b)[0]), "r"((b)[1]))

#define CP_ASYNC16(dst, src) \
    asm volatile("cp.async.cg.shared.global [%0], [%1], 16;" \
        :: "r"(dst), "l"(src) : "memory")
#define CP_COMMIT()  asm volatile("cp.async.commit_group;" ::: "memory")
#define CP_WAIT0()   asm volatile("cp.async.wait_group 0;" ::: "memory")

// ---------------- prepass: fp32 -> fp16 ----------------

__global__ void conv_w_kernel(const float* __restrict__ w) {
    int i = blockIdx.x * blockDim.x + threadIdx.x;
    if (i < OUT_C * NKDIM) g_wh[i] = __float2half(w[i]);
}

__global__ void conv_x_kernel(const float* __restrict__ x) {
    int i = blockIdx.x * blockDim.x + threadIdx.x;
    if (i >= 32 * IN_C * XPC) return;
    int iw = i % XPW;
    int t  = i / XPW;
    int ih = t % XPH;
    int c  = t / XPH;
    float v = 0.0f;
    if (ih >= 1 && ih <= HW && iw >= 1 && iw <= HW)
        v = x[c * SP + (ih - 1) * HW + (iw - 1)];
    g_xh[i] = __float2half(v);
}

// ---------------- staging ----------------

__device__ __forceinline__ void stage_chunk(
    uint32_t sbuf, int ch, int tid, int bm0,
    int cbase, int ngrp, int krow0)
{
    const int k0 = ch * BK;
    // A: weights, 128m x 32k fp16 = 512 x 16B, 2 cp.async per thread
    #pragma unroll
    for (int g = 0; g < 2; g++) {
        int idx = tid + 256 * g;            // 0..511
        int m   = idx >> 2;                 // 0..127
        int c4  = idx & 3;
        const char* src = (const char*)(g_wh + (bm0 + m) * NKDIM + k0) + c4 * 16;
        CP_ASYNC16(sbuf + m * A_STRIDE + c4 * 16, src);
    }
    CP_COMMIT();
    // B: im2col gather; each thread: 2 k-rows x 8 consecutive pixels
    const unsigned short* xh = (const unsigned short*)g_xh;
    #pragma unroll
    for (int kk = 0; kk < 2; kk++) {
        int krow = krow0 + kk * 16;         // 0..31
        int kg = k0 + krow;
        int ic = kg / 9;
        int r  = kg - ic * 9;
        int kh = r / 3;
        int kw = r - kh * 3;
        int base = cbase + ic * XPC + kh * XPW + kw;
        uint32_t p[4];
        #pragma unroll
        for (int j = 0; j < 4; j++)
            p[j] = (uint32_t)xh[base + 2*j] | ((uint32_t)xh[base + 2*j + 1] << 16);
        uint32_t dst = sbuf + A_BYTES + krow * B_STRIDE + ngrp * 16;
        asm volatile("st.shared.v4.b32 [%0], {%1,%2,%3,%4};"
                     :: "r"(dst), "r"(p[0]), "r"(p[1]), "r"(p[2]), "r"(p[3])
                     : "memory");
    }
}

// ---------------- main GEMM kernel ----------------

__global__ __launch_bounds__(THREADS, 2)
void conv_mma_kernel(const float* __restrict__ bias, float* __restrict__ out)
{
    extern __shared__ char smc[];
    const int tid = threadIdx.x;
    const int lid = tid & 31;
    const int wid = tid >> 5;
    const int bn0 = blockIdx.x * BN;
    const int bm0 = blockIdx.y * BM;
    const int wm0 = (wid >> 2) * 64;
    const int wn0 = (wid & 3) * 32;

    const int ngrp = tid & 15;
    const int krow0 = tid >> 4;             // 0..15
    int cbase;
    {
        int n0 = bn0 + ngrp * 8;
        int b  = n0 / SP;
        int s  = n0 - b * SP;
        int oh = s / HW;
        int ow0 = s - oh * HW;               // multiple of 8
        cbase = (b * IN_C) * XPC + oh * XPW + ow0;
    }

    const uint32_t sb = (uint32_t)__cvta_generic_to_shared(smc);

    float acc[4][4][4];
    #pragma unroll
    for (int mt = 0; mt < 4; mt++)
        #pragma unroll
        for (int nt = 0; nt < 4; nt++)
            #pragma unroll
            for (int q = 0; q < 4; q++)
                acc[mt][nt][q] = 0.0f;

    stage_chunk(sb, 0, tid, bm0, cbase, ngrp, krow0);
    CP_WAIT0();
    __syncthreads();

    int buf = 0;
    #pragma unroll 1
    for (int ch = 0; ch < NCH; ch++) {
        if (ch + 1 < NCH)
            stage_chunk(sb + (buf ^ 1) * BUF_BYTES, ch + 1, tid, bm0,
                        cbase, ngrp, krow0);

        const uint32_t ah = sb + buf * BUF_BYTES;
        const uint32_t bh = ah + A_BYTES;

        #pragma unroll
        for (int ks = 0; ks < 2; ks++) {
            uint32_t afr[4][4], bfr[4][2];
            const uint32_t aoff = (uint32_t)((wm0 + (lid & 15)) * A_STRIDE
                                             + ks * 32 + (lid >> 4) * 16);
            #pragma unroll
            for (int mt = 0; mt < 4; mt++)
                LDSM4(afr[mt], ah + aoff + mt * 16 * A_STRIDE);

            const uint32_t boff = (uint32_t)(
                (ks * 16 + (lid & 7) + ((lid >> 3) & 1) * 8) * B_STRIDE
                + (wn0 + (lid >> 4) * 8) * 2);
            LDSM4T(bfr[0][0], bfr[0][1], bfr[1][0], bfr[1][1], bh + boff);
            LDSM4T(bfr[2][0], bfr[2][1], bfr[3][0], bfr[3][1], bh + boff + 32);

            #pragma unroll
            for (int mt = 0; mt < 4; mt++)
                #pragma unroll
                for (int nt = 0; nt < 4; nt++)
                    MMA(acc[mt][nt], afr[mt], bfr[nt]);
        }
        CP_WAIT0();
        __syncthreads();
        buf ^= 1;
    }

    // epilogue: c-fragment direct stores (8B pairs)
    #pragma unroll
    for (int nt = 0; nt < 4; nt++) {
        int n = bn0 + wn0 + nt * 8 + 2 * (lid & 3);
        int b = n / SP;
        int s = n - b * SP;
        #pragma unroll
        for (int mt = 0; mt < 4; mt++) {
            int oc0 = bm0 + wm0 + mt * 16 + (lid >> 2);
            float bv0 = __ldg(&bias[oc0]);
            float bv1 = __ldg(&bias[oc0 + 8]);
            float2 v0 = make_float2(acc[mt][nt][0] + bv0, acc[mt][nt][1] + bv0);
            float2 v1 = make_float2(acc[mt][nt][2] + bv1, acc[mt][nt][3] + bv1);
            *(float2*)&out[(b * OUT_C + oc0) * SP + s] = v0;
            *(float2*)&out[(b * OUT_C + oc0 + 8) * SP + s] = v1;
        }
    }
}

extern "C" void kernel_launch(void* const* d_in, const int* in_sizes, int n_in,
                              void* d_out, int out_size)
{
    const float* x    = (const float*)d_in[0];
    const float* w    = (const float*)d_in[1];
    const float* bias = (const float*)d_in[2];
    float* out        = (float*)d_out;

    int wtot = OUT_C * NKDIM;
    conv_w_kernel<<<(wtot + 255) / 256, 256>>>(w);
    int xtot = 32 * IN_C * XPC;
    conv_x_kernel<<<(xtot + 255) / 256, 256>>>(x);

    cudaFuncSetAttribute(conv_mma_kernel,
                         cudaFuncAttributeMaxDynamicSharedMemorySize, SMEM_TOTAL);
    dim3 grid(NSPAT / BN, OUT_C / BM);      // 784 x 2
    conv_mma_kernel<<<grid, THREADS, SMEM_TOTAL>>>(bias, out);
}